// round 11
// baseline (speedup 1.0000x reference)
#include <cuda_runtime.h>
#include <cuda_bf16.h>

// A layout (smem): per patch 10 float4 payload + 1 pad => stride 11 float4.
// float4 m = ih*5+q holds { A[2ih][2q], A[2ih][2q+1], A[2ih+1][2q], A[2ih+1][2q+1] }.
// LDS.128: lane base = 11*lane (16B units), 3*lane mod 8 injective -> conflict-free.
#define P_STRIDE 44
#define A_FLOATS (196 * P_STRIDE)          // 8624 floats = 34.5 KB
#define B_TOTAL 8192
#define BLOCK_THREADS 512
#define IMGS_PER_BLOCK 32                  // 16 warps * 2 images
#define GRID_MAIN (B_TOTAL / IMGS_PER_BLOCK)   // 256 -> single resident wave

typedef unsigned long long ull;

__device__ __forceinline__ ull dup2(float v) {
    ull r; asm("mov.b64 %0, {%1, %1};" : "=l"(r) : "f"(v)); return r;
}
__device__ __forceinline__ void fma2(ull& d, ull a, ull b) {
    asm("fma.rn.f32x2 %0, %1, %2, %0;" : "+l"(d) : "l"(a), "l"(b));
}
__device__ __forceinline__ ull add2(ull a, ull b) {
    ull r; asm("add.rn.f32x2 %0, %1, %2;" : "=l"(r) : "l"(a), "l"(b)); return r;
}
__device__ __forceinline__ void upk2(float& lo, float& hi, ull v) {
    asm("mov.b64 {%0, %1}, %2;" : "=f"(lo), "=f"(hi) : "l"(v));
}

__global__ __launch_bounds__(BLOCK_THREADS, 2)
void fused_kernel(const float* __restrict__ x,
                  const float* __restrict__ var_params,
                  const float* __restrict__ map_w,
                  const float* __restrict__ map_b,
                  const float* __restrict__ lin_w,
                  const float* __restrict__ lin_b,
                  float* __restrict__ out) {
    __shared__ __align__(16) float As[A_FLOATS];
    __shared__ float trig[16];   // cv[0..3] sv[4..7] cw[8..11] sw[12..15]
    __shared__ float Cs[10];

    int tid  = threadIdx.x;
    int w    = tid >> 5;
    int lane = tid & 31;

    // ---- main-loop image pointers & iteration-0 x prefetch (overlaps prologue) ----
    int imgA = blockIdx.x * IMGS_PER_BLOCK + w * 2;
    const float* pa = x + (size_t)imgA * 784;
    const float* pb = pa + 784;

    float2 na0, na1, nb0, nb1;
    {
        int pr = lane / 14, pc = lane - pr * 14;
        int off = pr * 56 + pc * 2;
        na0 = __ldcs(reinterpret_cast<const float2*>(pa + off));
        na1 = __ldcs(reinterpret_cast<const float2*>(pa + off + 28));
        nb0 = __ldcs(reinterpret_cast<const float2*>(pb + off));
        nb1 = __ldcs(reinterpret_cast<const float2*>(pb + off + 28));
    }

    // ---- parallel trig ----
    if (tid < 8) {
        float s, c;
        sincosf(var_params[tid], &s, &c);
        int g = (tid < 4) ? 0 : 8;
        trig[g + (tid & 3)]     = c;
        trig[g + 4 + (tid & 3)] = s;
    }
    __syncthreads();

    // ---- every thread: Jacobian fold (redundant, ~100 flops) ----
    float Er[32];   // E[k][i] * (1/255)
    float qr[8];
    {
        float cv[4], sv[4], cw[4], sw[4];
#pragma unroll
        for (int j = 0; j < 4; j++) {
            cv[j] = trig[j];     sv[j] = trig[4 + j];
            cw[j] = trig[8 + j]; sw[j] = trig[12 + j];
        }
        float D[4][4];
#pragma unroll
        for (int j = 0; j < 4; j++)
#pragma unroll
            for (int i = 0; i < 4; i++) D[j][i] = 0.0f;
        D[0][0] = -cw[0]*sv[0] - sw[0]*cv[0]*sv[1];
        D[0][1] = -sw[0]*sv[0]*cv[1];
        D[1][0] = -cw[1]*sv[0]*cv[1];
        D[1][1] = -cw[1]*cv[0]*sv[1] - sw[1]*cv[1]*sv[2];
        D[1][2] = -sw[1]*sv[1]*cv[2];
        D[2][0] = -cw[2]*sv[0]*cv[1]*cv[2];
        D[2][1] = -cw[2]*cv[0]*sv[1]*cv[2];
        D[2][2] = -cw[2]*cv[0]*cv[1]*sv[2] - sw[2]*cv[2]*sv[3];
        D[2][3] = -sw[2]*sv[2]*cv[3];
        float P2c = cv[0]*cv[1]*cv[2];
        D[3][0] = -cw[3]*sv[0]*cv[1]*cv[2]*cv[3];
        D[3][1] = -cw[3]*cv[0]*sv[1]*cv[2]*cv[3];
        D[3][2] = -cw[3]*cv[0]*cv[1]*sv[2]*cv[3];
        D[3][3] = -cw[3]*P2c*sv[3] - sw[3]*cv[3];
        float z0v[4];
        z0v[0] = cw[0]*cv[0]       - sw[0]*sv[0]*sv[1];
        z0v[1] = cw[1]*cv[0]*cv[1] - sw[1]*sv[1]*sv[2];
        z0v[2] = cw[2]*P2c         - sw[2]*sv[2]*sv[3];
        z0v[3] = cw[3]*P2c*cv[3]   - sw[3]*sv[3];
#pragma unroll
        for (int k = 0; k < 8; k++) {
            float q = map_b[k];
#pragma unroll
            for (int j = 0; j < 4; j++) q += map_w[k*4 + j] * z0v[j];
            qr[k] = q;
#pragma unroll
            for (int i = 0; i < 4; i++) {
                float e = 0.0f;
#pragma unroll
                for (int j = 0; j < 4; j++) e += map_w[k*4 + j] * D[j][i];
                Er[k*4 + i] = e * (1.0f / 255.0f);
            }
        }
    }

    // ---- build A into smem, coalesced: slot = q*224 + p (warp-uniform q) ----
#pragma unroll
    for (int rep = 0; rep < 3; rep++) {
        int slot = tid + rep * BLOCK_THREADS;
        if (slot < 1120) {
            int q = slot / 224;
            int p = slot - q * 224;
            if (p < 196) {
                const float4* l0 = reinterpret_cast<const float4*>(
                    lin_w + (2*q) * 1568 + 8 * p);
                const float4* l1 = reinterpret_cast<const float4*>(
                    lin_w + (2*q + 1) * 1568 + 8 * p);
                float4 w00 = l0[0], w01 = l0[1];
                float4 w10 = l1[0], w11 = l1[1];
                float lw0[8] = {w00.x, w00.y, w00.z, w00.w, w01.x, w01.y, w01.z, w01.w};
                float lw1[8] = {w10.x, w10.y, w10.z, w10.w, w11.x, w11.y, w11.z, w11.w};
#pragma unroll
                for (int ih = 0; ih < 2; ih++) {
                    float rx = 0.f, ry = 0.f, rz = 0.f, rw = 0.f;
#pragma unroll
                    for (int k = 0; k < 8; k++) {
                        float e0 = Er[k*4 + 2*ih];
                        float e1 = Er[k*4 + 2*ih + 1];
                        rx += lw0[k] * e0;
                        ry += lw1[k] * e0;
                        rz += lw0[k] * e1;
                        rw += lw1[k] * e1;
                    }
                    *reinterpret_cast<float4*>(&As[p * P_STRIDE + (ih*5 + q) * 4]) =
                        make_float4(rx, ry, rz, rw);
                }
            }
        }
    }

    // ---- bias c: warp o (o < 10) reduces lin_w[o,:] . q[t%8] ----
    if (w < 10) {
        const float4* lw4 = reinterpret_cast<const float4*>(lin_w + w * 1568);
        float acc = 0.0f;
#pragma unroll
        for (int j = 0; j < 12; j++) {
            int idx = lane + j * 32;
            float4 v = lw4[idx];
            if (idx & 1)
                acc += v.x*qr[4] + v.y*qr[5] + v.z*qr[6] + v.w*qr[7];
            else
                acc += v.x*qr[0] + v.y*qr[1] + v.z*qr[2] + v.w*qr[3];
        }
        if (lane < 8) {
            int idx = 384 + lane;
            float4 v = lw4[idx];
            if (idx & 1)
                acc += v.x*qr[4] + v.y*qr[5] + v.z*qr[6] + v.w*qr[7];
            else
                acc += v.x*qr[0] + v.y*qr[1] + v.z*qr[2] + v.w*qr[3];
        }
#pragma unroll
        for (int s = 16; s; s >>= 1)
            acc += __shfl_xor_sync(0xFFFFFFFFu, acc, s);
        if (lane == 0) Cs[w] = acc + lin_b[w];
    }
    __syncthreads();

    // ---- main loop: warp = 2 images, p = lane + 32k, prefetch-1 ----
    ull accA[5], accB[5];
#pragma unroll
    for (int q = 0; q < 5; q++) { accA[q] = 0ull; accB[q] = 0ull; }

#pragma unroll
    for (int k = 0; k < 6; k++) {
        float2 a0 = na0, a1 = na1, b0 = nb0, b1 = nb1;
        if (k < 5) {            // prefetch k+1 before the FMA block
            int p  = lane + 32 * (k + 1);
            int pr = p / 14, pc = p - pr * 14;
            int off = pr * 56 + pc * 2;
            na0 = __ldcs(reinterpret_cast<const float2*>(pa + off));
            na1 = __ldcs(reinterpret_cast<const float2*>(pa + off + 28));
            nb0 = __ldcs(reinterpret_cast<const float2*>(pb + off));
            nb1 = __ldcs(reinterpret_cast<const float2*>(pb + off + 28));
        }
        int p = lane + 32 * k;
        ull da[4] = {dup2(a0.x), dup2(a0.y), dup2(a1.x), dup2(a1.y)};
        ull db[4] = {dup2(b0.x), dup2(b0.y), dup2(b1.x), dup2(b1.y)};
        const ulonglong2* wp =
            reinterpret_cast<const ulonglong2*>(&As[p * P_STRIDE]);
#pragma unroll
        for (int ih = 0; ih < 2; ih++) {
#pragma unroll
            for (int q = 0; q < 5; q++) {
                ulonglong2 v = wp[ih * 5 + q];   // LDS.128, conflict-free
                fma2(accA[q], v.x, da[2*ih]);
                fma2(accA[q], v.y, da[2*ih + 1]);
                fma2(accB[q], v.x, db[2*ih]);
                fma2(accB[q], v.y, db[2*ih + 1]);
            }
        }
    }
    // tail: p = 192..195 on lanes 0..3
    if (lane < 4) {
        int p = 192 + lane;
        int off = 13 * 56 + (10 + lane) * 2;
        float2 a0 = __ldcs(reinterpret_cast<const float2*>(pa + off));
        float2 a1 = __ldcs(reinterpret_cast<const float2*>(pa + off + 28));
        float2 b0 = __ldcs(reinterpret_cast<const float2*>(pb + off));
        float2 b1 = __ldcs(reinterpret_cast<const float2*>(pb + off + 28));
        ull da[4] = {dup2(a0.x), dup2(a0.y), dup2(a1.x), dup2(a1.y)};
        ull db[4] = {dup2(b0.x), dup2(b0.y), dup2(b1.x), dup2(b1.y)};
        const ulonglong2* wp =
            reinterpret_cast<const ulonglong2*>(&As[p * P_STRIDE]);
#pragma unroll
        for (int ih = 0; ih < 2; ih++) {
#pragma unroll
            for (int q = 0; q < 5; q++) {
                ulonglong2 v = wp[ih * 5 + q];
                fma2(accA[q], v.x, da[2*ih]);
                fma2(accA[q], v.y, da[2*ih + 1]);
                fma2(accB[q], v.x, db[2*ih]);
                fma2(accB[q], v.y, db[2*ih + 1]);
            }
        }
    }

    // ---- reduce: fold halves, split images across halves ----
    ull sel[5];
#pragma unroll
    for (int q = 0; q < 5; q++) {
        ull tA = add2(accA[q], __shfl_xor_sync(0xFFFFFFFFu, accA[q], 16));
        ull tB = add2(accB[q], __shfl_xor_sync(0xFFFFFFFFu, accB[q], 16));
        sel[q] = (lane < 16) ? tA : tB;
    }
#pragma unroll
    for (int q = 0; q < 5; q++) {
#pragma unroll
        for (int s = 8; s; s >>= 1)
            sel[q] = add2(sel[q], __shfl_xor_sync(0xFFFFFFFFu, sel[q], s));
    }

    // lane 0 -> imgA, lane 16 -> imgA+1
    if ((lane & 15) == 0) {
        int img = imgA + (lane >> 4);
        float l[10];
#pragma unroll
        for (int q = 0; q < 5; q++) upk2(l[2*q], l[2*q + 1], sel[q]);
        float mx = -1e30f;
#pragma unroll
        for (int o = 0; o < 10; o++) {
            l[o] += Cs[o];
            mx = fmaxf(mx, l[o]);
        }
        float sum = 0.0f;
#pragma unroll
        for (int o = 0; o < 10; o++) sum += __expf(l[o] - mx);
        float lse = mx + __logf(sum);
        float* op = out + (size_t)img * 10;
#pragma unroll
        for (int q = 0; q < 5; q++)
            __stcs(reinterpret_cast<float2*>(op) + q,
                   make_float2(l[2*q] - lse, l[2*q + 1] - lse));
    }
}

// ---------------------------------------------------------------------------
extern "C" void kernel_launch(void* const* d_in, const int* in_sizes, int n_in,
                              void* d_out, int out_size) {
    const float* x          = (const float*)d_in[0];
    const float* var_params = (const float*)d_in[1];
    const float* map_w      = (const float*)d_in[2];
    const float* map_b      = (const float*)d_in[3];
    const float* lin_w      = (const float*)d_in[4];
    const float* lin_b      = (const float*)d_in[5];
    float* out = (float*)d_out;

    fused_kernel<<<GRID_MAIN, BLOCK_THREADS>>>(x, var_params, map_w, map_b,
                                               lin_w, lin_b, out);
}

// round 12
// speedup vs baseline: 1.1382x; 1.1382x over previous
#include <cuda_runtime.h>
#include <cuda_bf16.h>

// A layout (smem): per patch 10 float4 payload + 1 pad => stride 11 float4 (44 floats).
// float4 m = ih*5+q holds { A[2ih][2q], A[2ih][2q+1], A[2ih+1][2q], A[2ih+1][2q+1] }.
// 8-lane LDS/STS.128 phases with stride 44 floats: 12*l mod 32 hits 8 distinct
// 4-word groups -> conflict-free.
#define P_STRIDE 44
#define A_FLOATS (196 * P_STRIDE)          // 8624 floats = 34.5 KB
#define B_TOTAL 8192
#define BLOCK_THREADS 256
#define IMGS_PER_BLOCK 32                  // 8 warps * 4 images
#define GRID_MAIN (B_TOTAL / IMGS_PER_BLOCK)   // 256 -> single resident wave

typedef unsigned long long ull;

__device__ __forceinline__ ull dup2(float v) {
    ull r; asm("mov.b64 %0, {%1, %1};" : "=l"(r) : "f"(v)); return r;
}
__device__ __forceinline__ void fma2(ull& d, ull a, ull b) {
    asm("fma.rn.f32x2 %0, %1, %2, %0;" : "+l"(d) : "l"(a), "l"(b));
}
__device__ __forceinline__ ull add2(ull a, ull b) {
    ull r; asm("add.rn.f32x2 %0, %1, %2;" : "=l"(r) : "l"(a), "l"(b)); return r;
}
__device__ __forceinline__ void upk2(float& lo, float& hi, ull v) {
    asm("mov.b64 {%0, %1}, %2;" : "=f"(lo), "=f"(hi) : "l"(v));
}

__global__ __launch_bounds__(BLOCK_THREADS, 2)
void fused_kernel(const float* __restrict__ x,
                  const float* __restrict__ var_params,
                  const float* __restrict__ map_w,
                  const float* __restrict__ map_b,
                  const float* __restrict__ lin_w,
                  const float* __restrict__ lin_b,
                  float* __restrict__ out) {
    __shared__ __align__(16) float As[A_FLOATS];
    __shared__ float trig[16];   // cv[0..3] sv[4..7] cw[8..11] sw[12..15]
    __shared__ float Cs[10];

    int tid  = threadIdx.x;
    int w    = tid >> 5;
    int lane = tid & 31;

    // ---- image pointers (float2-granular) + early prefetch of slots 0,1 ----
    int imgA = blockIdx.x * IMGS_PER_BLOCK + w * 4;
    const float2* pim2[4];
#pragma unroll
    for (int m = 0; m < 4; m++)
        pim2[m] = reinterpret_cast<const float2*>(x + (size_t)(imgA + m) * 784);

    float2 xb[2][4];   // depth-2 prefetch ring: xb[k&1][m] = float2 #(lane+32k)
#pragma unroll
    for (int s = 0; s < 2; s++) {
        int t = lane + 32 * s;
#pragma unroll
        for (int m = 0; m < 4; m++)
            xb[s][m] = __ldcs(pim2[m] + t);
    }

    // ---- parallel trig ----
    if (tid < 8) {
        float s, c;
        sincosf(var_params[tid], &s, &c);
        int g = (tid < 4) ? 0 : 8;
        trig[g + (tid & 3)]     = c;
        trig[g + 4 + (tid & 3)] = s;
    }
    __syncthreads();

    // ---- every thread: Jacobian fold (redundant, ~100 flops) ----
    float Er[32];   // E[k][i] * (1/255)
    float qr[8];
    {
        float cv[4], sv[4], cw[4], sw[4];
#pragma unroll
        for (int j = 0; j < 4; j++) {
            cv[j] = trig[j];     sv[j] = trig[4 + j];
            cw[j] = trig[8 + j]; sw[j] = trig[12 + j];
        }
        float D[4][4];
#pragma unroll
        for (int j = 0; j < 4; j++)
#pragma unroll
            for (int i = 0; i < 4; i++) D[j][i] = 0.0f;
        D[0][0] = -cw[0]*sv[0] - sw[0]*cv[0]*sv[1];
        D[0][1] = -sw[0]*sv[0]*cv[1];
        D[1][0] = -cw[1]*sv[0]*cv[1];
        D[1][1] = -cw[1]*cv[0]*sv[1] - sw[1]*cv[1]*sv[2];
        D[1][2] = -sw[1]*sv[1]*cv[2];
        D[2][0] = -cw[2]*sv[0]*cv[1]*cv[2];
        D[2][1] = -cw[2]*cv[0]*sv[1]*cv[2];
        D[2][2] = -cw[2]*cv[0]*cv[1]*sv[2] - sw[2]*cv[2]*sv[3];
        D[2][3] = -sw[2]*sv[2]*cv[3];
        float P2c = cv[0]*cv[1]*cv[2];
        D[3][0] = -cw[3]*sv[0]*cv[1]*cv[2]*cv[3];
        D[3][1] = -cw[3]*cv[0]*sv[1]*cv[2]*cv[3];
        D[3][2] = -cw[3]*cv[0]*cv[1]*sv[2]*cv[3];
        D[3][3] = -cw[3]*P2c*sv[3] - sw[3]*cv[3];
        float z0v[4];
        z0v[0] = cw[0]*cv[0]       - sw[0]*sv[0]*sv[1];
        z0v[1] = cw[1]*cv[0]*cv[1] - sw[1]*sv[1]*sv[2];
        z0v[2] = cw[2]*P2c         - sw[2]*sv[2]*sv[3];
        z0v[3] = cw[3]*P2c*cv[3]   - sw[3]*sv[3];
#pragma unroll
        for (int k = 0; k < 8; k++) {
            float q = map_b[k];
#pragma unroll
            for (int j = 0; j < 4; j++) q += map_w[k*4 + j] * z0v[j];
            qr[k] = q;
#pragma unroll
            for (int i = 0; i < 4; i++) {
                float e = 0.0f;
#pragma unroll
                for (int j = 0; j < 4; j++) e += map_w[k*4 + j] * D[j][i];
                Er[k*4 + i] = e * (1.0f / 255.0f);
            }
        }
    }

    // ---- build A into smem, coalesced: slot = q*224 + p (warp-uniform q) ----
#pragma unroll
    for (int rep = 0; rep < 5; rep++) {
        int slot = tid + rep * BLOCK_THREADS;
        if (slot < 1120) {
            int q = slot / 224;
            int p = slot - q * 224;
            if (p < 196) {
                const float4* l0 = reinterpret_cast<const float4*>(
                    lin_w + (2*q) * 1568 + 8 * p);
                const float4* l1 = reinterpret_cast<const float4*>(
                    lin_w + (2*q + 1) * 1568 + 8 * p);
                float4 w00 = l0[0], w01 = l0[1];
                float4 w10 = l1[0], w11 = l1[1];
                float lw0[8] = {w00.x, w00.y, w00.z, w00.w, w01.x, w01.y, w01.z, w01.w};
                float lw1[8] = {w10.x, w10.y, w10.z, w10.w, w11.x, w11.y, w11.z, w11.w};
#pragma unroll
                for (int ih = 0; ih < 2; ih++) {
                    float rx = 0.f, ry = 0.f, rz = 0.f, rw = 0.f;
#pragma unroll
                    for (int k = 0; k < 8; k++) {
                        float e0 = Er[k*4 + 2*ih];
                        float e1 = Er[k*4 + 2*ih + 1];
                        rx += lw0[k] * e0;
                        ry += lw1[k] * e0;
                        rz += lw0[k] * e1;
                        rw += lw1[k] * e1;
                    }
                    *reinterpret_cast<float4*>(&As[p * P_STRIDE + (ih*5 + q) * 4]) =
                        make_float4(rx, ry, rz, rw);
                }
            }
        }
    }

    // ---- bias c: warp w reduces lin_w[o,:] . q[t%8] for o = w, w+8 ----
    for (int o = w; o < 10; o += 8) {
        const float4* lw4 = reinterpret_cast<const float4*>(lin_w + o * 1568);
        float acc = 0.0f;
#pragma unroll
        for (int j = 0; j < 12; j++) {
            int idx = lane + j * 32;
            float4 v = lw4[idx];
            if (idx & 1)
                acc += v.x*qr[4] + v.y*qr[5] + v.z*qr[6] + v.w*qr[7];
            else
                acc += v.x*qr[0] + v.y*qr[1] + v.z*qr[2] + v.w*qr[3];
        }
        if (lane < 8) {
            int idx = 384 + lane;
            float4 v = lw4[idx];
            if (idx & 1)
                acc += v.x*qr[4] + v.y*qr[5] + v.z*qr[6] + v.w*qr[7];
            else
                acc += v.x*qr[0] + v.y*qr[1] + v.z*qr[2] + v.w*qr[3];
        }
#pragma unroll
        for (int s = 16; s; s >>= 1)
            acc += __shfl_xor_sync(0xFFFFFFFFu, acc, s);
        if (lane == 0) Cs[o] = acc + lin_b[o];
    }
    __syncthreads();

    // ---- main loop: t-indexed (dense 256B warp loads), half-patch units ----
    // float2 #t = pixels (2t, 2t+1): r=t/14, c=t%14 -> patch p=(r>>1)*14+c,
    // half ih=r&1. A unit for (p, ih) = 5 ulonglong2 at As[p*44 + ih*20].
    ull acc[4][5];
#pragma unroll
    for (int m = 0; m < 4; m++)
#pragma unroll
        for (int q = 0; q < 5; q++) acc[m][q] = 0ull;

#pragma unroll
    for (int k = 0; k < 12; k++) {
        int s = k & 1;
        float2 cur[4];
#pragma unroll
        for (int m = 0; m < 4; m++) cur[m] = xb[s][m];
        if (k < 10) {                       // prefetch t(k+2) into freed slot
            int tn = lane + 32 * (k + 2);
#pragma unroll
            for (int m = 0; m < 4; m++)
                xb[s][m] = __ldcs(pim2[m] + tn);
        }
        int t  = lane + 32 * k;
        int r  = t / 14;
        int c  = t - r * 14;
        int p  = (r >> 1) * 14 + c;
        int ih = r & 1;
        const ulonglong2* wp =
            reinterpret_cast<const ulonglong2*>(&As[p * P_STRIDE + ih * 20]);
        ull d0[4], d1[4];
#pragma unroll
        for (int m = 0; m < 4; m++) {
            d0[m] = dup2(cur[m].x);        // pixel i = 2*ih
            d1[m] = dup2(cur[m].y);        // pixel i = 2*ih+1
        }
#pragma unroll
        for (int q = 0; q < 5; q++) {
            ulonglong2 v = wp[q];          // conflict-free LDS.128
#pragma unroll
            for (int m = 0; m < 4; m++) {
                fma2(acc[m][q], v.x, d0[m]);
                fma2(acc[m][q], v.y, d1[m]);
            }
        }
    }
    // tail: t = 384..391 on lanes 0..7 (r=27, ih=1, p=188..195)
    if (lane < 8) {
        int t  = 384 + lane;
        int c  = t - 378;                  // r = 27
        int p  = 182 + c;
        const ulonglong2* wp =
            reinterpret_cast<const ulonglong2*>(&As[p * P_STRIDE + 20]);
        ull d0[4], d1[4];
#pragma unroll
        for (int m = 0; m < 4; m++) {
            float2 v2 = __ldcs(pim2[m] + t);
            d0[m] = dup2(v2.x);
            d1[m] = dup2(v2.y);
        }
#pragma unroll
        for (int q = 0; q < 5; q++) {
            ulonglong2 v = wp[q];
#pragma unroll
            for (int m = 0; m < 4; m++) {
                fma2(acc[m][q], v.x, d0[m]);
                fma2(acc[m][q], v.y, d1[m]);
            }
        }
    }

    // ---- reduce: 4 images folded into eighths of the warp ----
    ull sel[5];
#pragma unroll
    for (int q = 0; q < 5; q++) {
        ull t0 = add2(acc[0][q], __shfl_xor_sync(0xFFFFFFFFu, acc[0][q], 16));
        ull t1 = add2(acc[1][q], __shfl_xor_sync(0xFFFFFFFFu, acc[1][q], 16));
        ull t2 = add2(acc[2][q], __shfl_xor_sync(0xFFFFFFFFu, acc[2][q], 16));
        ull t3 = add2(acc[3][q], __shfl_xor_sync(0xFFFFFFFFu, acc[3][q], 16));
        ull lo = (lane < 16) ? t0 : t2;
        ull hi = (lane < 16) ? t1 : t3;
        lo = add2(lo, __shfl_xor_sync(0xFFFFFFFFu, lo, 8));
        hi = add2(hi, __shfl_xor_sync(0xFFFFFFFFu, hi, 8));
        ull s2 = (lane & 8) ? hi : lo;
        s2 = add2(s2, __shfl_xor_sync(0xFFFFFFFFu, s2, 4));
        s2 = add2(s2, __shfl_xor_sync(0xFFFFFFFFu, s2, 2));
        s2 = add2(s2, __shfl_xor_sync(0xFFFFFFFFu, s2, 1));
        sel[q] = s2;
    }

    // lanes 0,8,16,24 hold images imgA+0..3
    if ((lane & 7) == 0) {
        int img = imgA + (lane >> 3);
        float l[10];
#pragma unroll
        for (int q = 0; q < 5; q++) upk2(l[2*q], l[2*q + 1], sel[q]);
        float mx = -1e30f;
#pragma unroll
        for (int o = 0; o < 10; o++) {
            l[o] += Cs[o];
            mx = fmaxf(mx, l[o]);
        }
        float sum = 0.0f;
#pragma unroll
        for (int o = 0; o < 10; o++) sum += __expf(l[o] - mx);
        float lse = mx + __logf(sum);
        float* op = out + (size_t)img * 10;
#pragma unroll
        for (int q = 0; q < 5; q++)
            __stcs(reinterpret_cast<float2*>(op) + q,
                   make_float2(l[2*q] - lse, l[2*q + 1] - lse));
    }
}

// ---------------------------------------------------------------------------
extern "C" void kernel_launch(void* const* d_in, const int* in_sizes, int n_in,
                              void* d_out, int out_size) {
    const float* x          = (const float*)d_in[0];
    const float* var_params = (const float*)d_in[1];
    const float* map_w      = (const float*)d_in[2];
    const float* map_b      = (const float*)d_in[3];
    const float* lin_w      = (const float*)d_in[4];
    const float* lin_b      = (const float*)d_in[5];
    float* out = (float*)d_out;

    fused_kernel<<<GRID_MAIN, BLOCK_THREADS>>>(x, var_params, map_w, map_b,
                                               lin_w, lin_b, out);
}